// round 9
// baseline (speedup 1.0000x reference)
#include <cuda_runtime.h>

// SE3 transform at the HBM roofline (~6.4 TB/s measured ceiling on this
// read+write mix). One float4 column chunk per thread per row, 4 independent
// LDG.128 + 4 STG.128, fully coalesced. Matrix rebuilt per thread in closed
// form (free under memory-bound issue slack):
//   R = I + s K + a (w w^T - |w|^2 I),            a = 1 - cos th
//   t = th v + a (w x v) + b (w (w.v) - |w|^2 v), b = th - sin th
// Bottom row of M is [0,0,0,1] => output row 3 = input row 3.

struct SE3M {
    float R0,R1,R2,R3,R4,R5,R6,R7,R8,t0,t1,t2;
};

__device__ __forceinline__ SE3M build_M(const float* __restrict__ w,
                                        const float* __restrict__ v,
                                        const float* __restrict__ theta)
{
    const float wx = __ldg(&w[0]), wy = __ldg(&w[1]), wz = __ldg(&w[2]);
    const float vx = __ldg(&v[0]), vy = __ldg(&v[1]), vz = __ldg(&v[2]);
    const float th = __ldg(&theta[0]);
    const float s = sinf(th);
    const float c = cosf(th);
    const float a = 1.0f - c;
    const float b = th - s;
    const float n2 = wx*wx + wy*wy + wz*wz;

    SE3M m;
    m.R0 = 1.0f + a*(wx*wx - n2);
    m.R1 = -s*wz + a*(wx*wy);
    m.R2 =  s*wy + a*(wx*wz);
    m.R3 =  s*wz + a*(wy*wx);
    m.R4 = 1.0f + a*(wy*wy - n2);
    m.R5 = -s*wx + a*(wy*wz);
    m.R6 = -s*wy + a*(wz*wx);
    m.R7 =  s*wx + a*(wz*wy);
    m.R8 = 1.0f + a*(wz*wz - n2);

    const float wv = wx*vx + wy*vy + wz*vz;
    m.t0 = th*vx + a*(wy*vz - wz*vy) + b*(wx*wv - n2*vx);
    m.t1 = th*vy + a*(wz*vx - wx*vz) + b*(wy*wv - n2*vy);
    m.t2 = th*vz + a*(wx*vy - wy*vx) + b*(wz*wv - n2*vz);
    return m;
}

__device__ __forceinline__ void apply_chunk(const SE3M& m,
                                            const float4* __restrict__ x,
                                            float4* __restrict__ y,
                                            long long i, long long n4)
{
    const float4 r0 = __ldcs(&x[i]);
    const float4 r1 = __ldcs(&x[i + n4]);
    const float4 r2 = __ldcs(&x[i + 2*n4]);
    const float4 r3 = __ldcs(&x[i + 3*n4]);

    float4 o0, o1, o2;
    o0.x = m.R0*r0.x + m.R1*r1.x + m.R2*r2.x + m.t0*r3.x;
    o0.y = m.R0*r0.y + m.R1*r1.y + m.R2*r2.y + m.t0*r3.y;
    o0.z = m.R0*r0.z + m.R1*r1.z + m.R2*r2.z + m.t0*r3.z;
    o0.w = m.R0*r0.w + m.R1*r1.w + m.R2*r2.w + m.t0*r3.w;

    o1.x = m.R3*r0.x + m.R4*r1.x + m.R5*r2.x + m.t1*r3.x;
    o1.y = m.R3*r0.y + m.R4*r1.y + m.R5*r2.y + m.t1*r3.y;
    o1.z = m.R3*r0.z + m.R4*r1.z + m.R5*r2.z + m.t1*r3.z;
    o1.w = m.R3*r0.w + m.R4*r1.w + m.R5*r2.w + m.t1*r3.w;

    o2.x = m.R6*r0.x + m.R7*r1.x + m.R8*r2.x + m.t2*r3.x;
    o2.y = m.R6*r0.y + m.R7*r1.y + m.R8*r2.y + m.t2*r3.y;
    o2.z = m.R6*r0.z + m.R7*r1.z + m.R8*r2.z + m.t2*r3.z;
    o2.w = m.R6*r0.w + m.R7*r1.w + m.R8*r2.w + m.t2*r3.w;

    __stcs(&y[i],        o0);
    __stcs(&y[i + n4],   o1);
    __stcs(&y[i + 2*n4], o2);
    __stcs(&y[i + 3*n4], r3);   // bottom row = [0,0,0,1]
}

// Fast path: n divisible by 4 AND n4 divisible by blockDim — no predicates.
__global__ __launch_bounds__(256)
void se3_exact_kernel(const float4* __restrict__ x,
                      float4* __restrict__ y,
                      const float* __restrict__ w,
                      const float* __restrict__ v,
                      const float* __restrict__ theta,
                      long long n4)
{
    const SE3M m = build_M(w, v, theta);
    const long long i = (long long)blockIdx.x * blockDim.x + threadIdx.x;
    apply_chunk(m, x, y, i, n4);
}

// Generic path: bounds-checked chunks + scalar tail.
__global__ __launch_bounds__(256)
void se3_generic_kernel(const float4* __restrict__ x,
                        float4* __restrict__ y,
                        const float* __restrict__ w,
                        const float* __restrict__ v,
                        const float* __restrict__ theta,
                        long long n, long long n4)
{
    const SE3M m = build_M(w, v, theta);
    const long long i = (long long)blockIdx.x * blockDim.x + threadIdx.x;
    if (i < n4) apply_chunk(m, x, y, i, n4);

    const long long tail = n - 4*n4;
    if (i < tail) {
        const float* xf = (const float*)x;
        float* yf = (float*)y;
        const long long j = 4*n4 + i;
        const float x0 = xf[0*n + j];
        const float x1 = xf[1*n + j];
        const float x2 = xf[2*n + j];
        const float x3 = xf[3*n + j];
        yf[0*n + j] = m.R0*x0 + m.R1*x1 + m.R2*x2 + m.t0*x3;
        yf[1*n + j] = m.R3*x0 + m.R4*x1 + m.R5*x2 + m.t1*x3;
        yf[2*n + j] = m.R6*x0 + m.R7*x1 + m.R8*x2 + m.t2*x3;
        yf[3*n + j] = x3;
    }
}

extern "C" void kernel_launch(void* const* d_in, const int* in_sizes, int n_in,
                              void* d_out, int out_size)
{
    const float* x     = (const float*)d_in[0];   // [4, N]
    const float* w     = (const float*)d_in[1];   // [3]
    const float* v     = (const float*)d_in[2];   // [3]
    const float* theta = (const float*)d_in[3];   // []
    float* y = (float*)d_out;                     // [4, N]

    const long long n  = (long long)in_sizes[0] / 4;  // N columns
    const long long n4 = n / 4;                       // float4 chunks per row
    const int threads = 256;

    if ((n % 4) == 0 && (n4 % threads) == 0) {
        const long long blocks = n4 / threads;
        se3_exact_kernel<<<(unsigned int)blocks, threads>>>(
            (const float4*)x, (float4*)y, w, v, theta, n4);
    } else {
        const long long blocks = (n4 + threads - 1) / threads;
        se3_generic_kernel<<<(unsigned int)(blocks > 0 ? blocks : 1), threads>>>(
            (const float4*)x, (float4*)y, w, v, theta, n, n4);
    }
}

// round 10
// speedup vs baseline: 1.0008x; 1.0008x over previous
#include <cuda_runtime.h>

// SE3 transform at the HBM roofline (~6.4 TB/s measured ceiling on this
// read+write mix). One float4 column chunk per thread per row, 4 independent
// LDG.128 + 4 STG.128, fully coalesced. Matrix rebuilt per thread in closed
// form (free under memory-bound issue slack):
//   R = I + s K + a (w w^T - |w|^2 I),            a = 1 - cos th
//   t = th v + a (w x v) + b (w (w.v) - |w|^2 v), b = th - sin th
// Bottom row of M is [0,0,0,1] => output row 3 = input row 3.

struct SE3M {
    float R0,R1,R2,R3,R4,R5,R6,R7,R8,t0,t1,t2;
};

__device__ __forceinline__ SE3M build_M(const float* __restrict__ w,
                                        const float* __restrict__ v,
                                        const float* __restrict__ theta)
{
    const float wx = __ldg(&w[0]), wy = __ldg(&w[1]), wz = __ldg(&w[2]);
    const float vx = __ldg(&v[0]), vy = __ldg(&v[1]), vz = __ldg(&v[2]);
    const float th = __ldg(&theta[0]);
    const float s = sinf(th);
    const float c = cosf(th);
    const float a = 1.0f - c;
    const float b = th - s;
    const float n2 = wx*wx + wy*wy + wz*wz;

    SE3M m;
    m.R0 = 1.0f + a*(wx*wx - n2);
    m.R1 = -s*wz + a*(wx*wy);
    m.R2 =  s*wy + a*(wx*wz);
    m.R3 =  s*wz + a*(wy*wx);
    m.R4 = 1.0f + a*(wy*wy - n2);
    m.R5 = -s*wx + a*(wy*wz);
    m.R6 = -s*wy + a*(wz*wx);
    m.R7 =  s*wx + a*(wz*wy);
    m.R8 = 1.0f + a*(wz*wz - n2);

    const float wv = wx*vx + wy*vy + wz*vz;
    m.t0 = th*vx + a*(wy*vz - wz*vy) + b*(wx*wv - n2*vx);
    m.t1 = th*vy + a*(wz*vx - wx*vz) + b*(wy*wv - n2*vy);
    m.t2 = th*vz + a*(wx*vy - wy*vx) + b*(wz*wv - n2*vz);
    return m;
}

__device__ __forceinline__ void apply_chunk(const SE3M& m,
                                            const float4* __restrict__ x,
                                            float4* __restrict__ y,
                                            long long i, long long n4)
{
    const float4 r0 = __ldcs(&x[i]);
    const float4 r1 = __ldcs(&x[i + n4]);
    const float4 r2 = __ldcs(&x[i + 2*n4]);
    const float4 r3 = __ldcs(&x[i + 3*n4]);

    float4 o0, o1, o2;
    o0.x = m.R0*r0.x + m.R1*r1.x + m.R2*r2.x + m.t0*r3.x;
    o0.y = m.R0*r0.y + m.R1*r1.y + m.R2*r2.y + m.t0*r3.y;
    o0.z = m.R0*r0.z + m.R1*r1.z + m.R2*r2.z + m.t0*r3.z;
    o0.w = m.R0*r0.w + m.R1*r1.w + m.R2*r2.w + m.t0*r3.w;

    o1.x = m.R3*r0.x + m.R4*r1.x + m.R5*r2.x + m.t1*r3.x;
    o1.y = m.R3*r0.y + m.R4*r1.y + m.R5*r2.y + m.t1*r3.y;
    o1.z = m.R3*r0.z + m.R4*r1.z + m.R5*r2.z + m.t1*r3.z;
    o1.w = m.R3*r0.w + m.R4*r1.w + m.R5*r2.w + m.t1*r3.w;

    o2.x = m.R6*r0.x + m.R7*r1.x + m.R8*r2.x + m.t2*r3.x;
    o2.y = m.R6*r0.y + m.R7*r1.y + m.R8*r2.y + m.t2*r3.y;
    o2.z = m.R6*r0.z + m.R7*r1.z + m.R8*r2.z + m.t2*r3.z;
    o2.w = m.R6*r0.w + m.R7*r1.w + m.R8*r2.w + m.t2*r3.w;

    __stcs(&y[i],        o0);
    __stcs(&y[i + n4],   o1);
    __stcs(&y[i + 2*n4], o2);
    __stcs(&y[i + 3*n4], r3);   // bottom row = [0,0,0,1]
}

// Fast path: n divisible by 4 AND n4 divisible by blockDim — no predicates.
__global__ __launch_bounds__(256)
void se3_exact_kernel(const float4* __restrict__ x,
                      float4* __restrict__ y,
                      const float* __restrict__ w,
                      const float* __restrict__ v,
                      const float* __restrict__ theta,
                      long long n4)
{
    const SE3M m = build_M(w, v, theta);
    const long long i = (long long)blockIdx.x * blockDim.x + threadIdx.x;
    apply_chunk(m, x, y, i, n4);
}

// Generic path: bounds-checked chunks + scalar tail.
__global__ __launch_bounds__(256)
void se3_generic_kernel(const float4* __restrict__ x,
                        float4* __restrict__ y,
                        const float* __restrict__ w,
                        const float* __restrict__ v,
                        const float* __restrict__ theta,
                        long long n, long long n4)
{
    const SE3M m = build_M(w, v, theta);
    const long long i = (long long)blockIdx.x * blockDim.x + threadIdx.x;
    if (i < n4) apply_chunk(m, x, y, i, n4);

    const long long tail = n - 4*n4;
    if (i < tail) {
        const float* xf = (const float*)x;
        float* yf = (float*)y;
        const long long j = 4*n4 + i;
        const float x0 = xf[0*n + j];
        const float x1 = xf[1*n + j];
        const float x2 = xf[2*n + j];
        const float x3 = xf[3*n + j];
        yf[0*n + j] = m.R0*x0 + m.R1*x1 + m.R2*x2 + m.t0*x3;
        yf[1*n + j] = m.R3*x0 + m.R4*x1 + m.R5*x2 + m.t1*x3;
        yf[2*n + j] = m.R6*x0 + m.R7*x1 + m.R8*x2 + m.t2*x3;
        yf[3*n + j] = x3;
    }
}

extern "C" void kernel_launch(void* const* d_in, const int* in_sizes, int n_in,
                              void* d_out, int out_size)
{
    const float* x     = (const float*)d_in[0];   // [4, N]
    const float* w     = (const float*)d_in[1];   // [3]
    const float* v     = (const float*)d_in[2];   // [3]
    const float* theta = (const float*)d_in[3];   // []
    float* y = (float*)d_out;                     // [4, N]

    const long long n  = (long long)in_sizes[0] / 4;  // N columns
    const long long n4 = n / 4;                       // float4 chunks per row
    const int threads = 256;

    if ((n % 4) == 0 && (n4 % threads) == 0) {
        const long long blocks = n4 / threads;
        se3_exact_kernel<<<(unsigned int)blocks, threads>>>(
            (const float4*)x, (float4*)y, w, v, theta, n4);
    } else {
        const long long blocks = (n4 + threads - 1) / threads;
        se3_generic_kernel<<<(unsigned int)(blocks > 0 ? blocks : 1), threads>>>(
            (const float4*)x, (float4*)y, w, v, theta, n, n4);
    }
}